// round 5
// baseline (speedup 1.0000x reference)
#include <cuda_runtime.h>
#include <cuda_bf16.h>
#include <math.h>

#define V_  5
#define C_  32
#define H_  384
#define W_  384
#define D_  4
#define G_  8
#define HW_ (H_ * W_)          // 147456
#define NTB (HW_ / 32)         // transpose blocks per view: 4608

// Transposed features (V, H*W, C): per-pixel channels contiguous, fp32.
__device__ float g_featT[(size_t)V_ * HW_ * C_];   // ~94.4 MB
// Folded projection per source view: uvd = M_s * (gx,gy,1) * dep + c_s
__device__ float g_M[4][9];
__device__ float g_c[4][3];

__device__ __forceinline__ void invert3d(const double* m, double* inv) {
    double a = m[0], b = m[1], c = m[2];
    double d = m[3], e = m[4], f = m[5];
    double g = m[6], h = m[7], i = m[8];
    double A  =  (e*i - f*h);
    double Bc = -(d*i - f*g);
    double Cc =  (d*h - e*g);
    double det = a*A + b*Bc + c*Cc;
    double id = 1.0 / det;
    inv[0] = A * id;
    inv[1] = -(b*i - c*h) * id;
    inv[2] =  (b*f - c*e) * id;
    inv[3] = Bc * id;
    inv[4] =  (a*i - c*g) * id;
    inv[5] = -(a*f - c*d) * id;
    inv[6] = Cc * id;
    inv[7] = -(a*h - b*g) * id;
    inv[8] =  (a*e - b*d) * id;
}

__device__ __forceinline__ void mat3mul(const double* A, const double* B, double* Cm) {
    #pragma unroll
    for (int i = 0; i < 3; i++)
        #pragma unroll
        for (int j = 0; j < 3; j++)
            Cm[i*3+j] = A[i*3+0]*B[0*3+j] + A[i*3+1]*B[1*3+j] + A[i*3+2]*B[2*3+j];
}

// Fused: blocks [0, NTB*V) transpose CHW->HWC; block NTB*V does camera setup
// (fp64 math on 4 threads; spills to local are fine, hidden under the wave).
__global__ void __launch_bounds__(1024)
transpose_setup_kernel(const float* __restrict__ f,
                       const float* __restrict__ K,
                       const float* __restrict__ E) {
    if (blockIdx.x == NTB * V_) {
        const int s = threadIdx.x + threadIdx.y * 32;
        if (s < 4) {
            double K0[9], Kinv[9], R0[9], Rinv[9], t0[3];
            #pragma unroll
            for (int i = 0; i < 9; i++) K0[i] = (double)K[i];
            invert3d(K0, Kinv);
            #pragma unroll
            for (int i = 0; i < 3; i++) {
                #pragma unroll
                for (int j = 0; j < 3; j++) R0[i*3+j] = (double)E[i*4+j];
                t0[i] = (double)E[i*4+3];
            }
            invert3d(R0, Rinv);

            double Ks[9], Rs[9], ts[3];
            #pragma unroll
            for (int i = 0; i < 9; i++) Ks[i] = (double)K[(s+1)*9 + i];
            #pragma unroll
            for (int i = 0; i < 3; i++) {
                #pragma unroll
                for (int j = 0; j < 3; j++) Rs[i*3+j] = (double)E[(s+1)*12 + i*4 + j];
                ts[i] = (double)E[(s+1)*12 + i*4 + 3];
            }
            double A[9], Bm[9], M[9];
            mat3mul(Rs, Rinv, A);
            mat3mul(Ks, A, Bm);
            mat3mul(Bm, Kinv, M);
            #pragma unroll
            for (int i = 0; i < 3; i++) {
                double kt = Ks[i*3+0]*ts[0] + Ks[i*3+1]*ts[1] + Ks[i*3+2]*ts[2];
                double bt = Bm[i*3+0]*t0[0] + Bm[i*3+1]*t0[1] + Bm[i*3+2]*t0[2];
                g_c[s][i] = (float)(kt - bt);
            }
            #pragma unroll
            for (int i = 0; i < 9; i++) g_M[s][i] = (float)M[i];
        }
        return;
    }
    __shared__ float sbuf[32][33];
    const int v  = blockIdx.x / NTB;
    const int p0 = (blockIdx.x - v * NTB) * 32;
    const int tx = threadIdx.x, ty = threadIdx.y;
    sbuf[ty][tx] = f[((size_t)v * C_ + ty) * HW_ + p0 + tx];
    __syncthreads();
    g_featT[(size_t)v * HW_ * C_ + (size_t)(p0 + ty) * C_ + tx] = sbuf[tx][ty];
}

// Main kernel: 256 threads = 32 pixels x 8 group-lanes.
__global__ void __launch_bounds__(256, 5)
gbinet_main_kernel(const float* __restrict__ depths,
                   const float* __restrict__ w0, const float* __restrict__ b0,
                   const float* __restrict__ w1, const float* __restrict__ b1,
                   const float* __restrict__ w2, const float* __restrict__ b2,
                   float* __restrict__ out) {
    __shared__ float sw0[16*8], sb0[16], sw1[8*16], sb1[8], sw2[8], sb2v[1];
    __shared__ float sM[4][9], sc[4][3];
    __shared__ float ssim[4 * 4 * 32 * 9];   // [s][d][pixL][g(pad 9)] = 18 KB
    __shared__ float ssig[4 * 4 * 32];       // [s][d][pixL]
    __shared__ float svw[4 * 32];            // [s][pixL]

    const int tid  = threadIdx.x;
    const int pixL = tid >> 3;
    const int g    = tid & 7;

    if (tid < 128) sw0[tid] = w0[tid];
    else           sw1[tid - 128] = w1[tid - 128];
    if (tid < 16) sb0[tid] = b0[tid];
    if (tid >= 16 && tid < 24) sb1[tid - 16] = b1[tid - 16];
    if (tid >= 24 && tid < 32) sw2[tid - 24] = w2[tid - 24];
    if (tid == 32) sb2v[0] = b2[0];
    if (tid >= 64 && tid < 64 + 36) {
        int i = tid - 64; sM[i / 9][i % 9] = g_M[i / 9][i % 9];
    }
    if (tid >= 100 && tid < 112) {
        int i = tid - 100; sc[i / 3][i % 3] = g_c[i / 3][i % 3];
    }

    const int pix = blockIdx.x * 32 + pixL;
    const int y = pix / W_;
    const int x = pix - y * W_;
    const float gx = (float)x + 0.5f;
    const float gy = (float)y + 0.5f;

    float dep[D_];
    #pragma unroll
    for (int d = 0; d < D_; d++) dep[d] = depths[d * HW_ + pix];

    const float4* __restrict__ fT4 = (const float4*)g_featT;
    const float4 ref = fT4[(size_t)pix * 8 + g];

    __syncthreads();   // weights + M/c visible

    // ---- gather phase: branchless bilinear, loads batched per view ----
    for (int s = 0; s < 4; s++) {
        const float mx = sM[s][0]*gx + sM[s][1]*gy + sM[s][2];
        const float my = sM[s][3]*gx + sM[s][4]*gy + sM[s][5];
        const float mz = sM[s][6]*gx + sM[s][7]*gy + sM[s][8];
        const size_t vbase = (size_t)(s + 1) * HW_;
        #pragma unroll
        for (int d = 0; d < D_; d++) {
            const float uh = fmaf(mx, dep[d], sc[s][0]);
            const float vh = fmaf(my, dep[d], sc[s][1]);
            const float zh = fmaf(mz, dep[d], sc[s][2]);
            const float rz = 1.0f / (zh + 1e-9f);
            const float px = uh * rz;
            const float py = vh * rz;

            const float x0f = floorf(px);
            const float y0f = floorf(py);
            const float wx1 = px - x0f, wx0v = 1.0f - wx1;
            const float wy1 = py - y0f, wy0v = 1.0f - wy1;

            float acc = 0.0f;
            #pragma unroll
            for (int corner = 0; corner < 4; corner++) {
                const float xf = x0f + (float)(corner & 1);
                const float yf = y0f + (float)(corner >> 1);
                float w = ((corner & 1) ? wx1 : wx0v) *
                          ((corner >> 1) ? wy1 : wy0v);
                const bool valid = (xf >= 0.0f) & (xf <= (float)(W_ - 1)) &
                                   (yf >= 0.0f) & (yf <= (float)(H_ - 1));
                w = valid ? w : 0.0f;
                const int xi = min(max((int)xf, 0), W_ - 1);
                const int yi = min(max((int)yf, 0), H_ - 1);
                const float4 f = __ldg(fT4 + (vbase + (size_t)yi * W_ + xi) * 8 + g);
                const float dot = f.x*ref.x + f.y*ref.y + f.z*ref.z + f.w*ref.w;
                acc = fmaf(w, dot, acc);
            }
            ssim[((s * 4 + d) * 32 + pixL) * 9 + g] = 0.25f * acc;
        }
    }
    __syncthreads();

    // ---- MLP phase: 512 (s,d,pix) items over 256 threads, 2 each ----
    #pragma unroll
    for (int it = 0; it < 2; it++) {
        const int i  = tid + it * 256;
        const int pp = i & 31;
        const int d  = (i >> 5) & 3;
        const int s  = i >> 7;
        const int base = ((s * 4 + d) * 32 + pp) * 9;
        float sv[8];
        #pragma unroll
        for (int k = 0; k < 8; k++) sv[k] = ssim[base + k];

        float x0v[16];
        #pragma unroll
        for (int o = 0; o < 16; o++) {
            float t = sb0[o];
            #pragma unroll
            for (int k = 0; k < 8; k++) t = fmaf(sw0[o*8 + k], sv[k], t);
            x0v[o] = fmaxf(t, 0.0f);
        }
        float x1v[8];
        #pragma unroll
        for (int j = 0; j < 8; j++) {
            float t = sb1[j];
            #pragma unroll
            for (int o = 0; o < 16; o++) t = fmaf(sw1[j*16 + o], x0v[o], t);
            x1v[j] = fmaxf(t, 0.0f);
        }
        float yv = sb2v[0];
        #pragma unroll
        for (int j = 0; j < 8; j++) yv = fmaf(sw2[j], x1v[j], yv);
        ssig[(s * 4 + d) * 32 + pp] = 1.0f / (1.0f + expf(-yv));
    }
    __syncthreads();

    // ---- depth max: vw[s][pix] = max_d sigmoid ----
    if (tid < 128) {
        const int s  = tid >> 5;
        const int pp = tid & 31;
        float m = ssig[(s * 4 + 0) * 32 + pp];
        #pragma unroll
        for (int d = 1; d < 4; d++) m = fmaxf(m, ssig[(s * 4 + d) * 32 + pp]);
        svw[s * 32 + pp] = m;
    }
    __syncthreads();

    // ---- accumulate + output ----
    float simsum[D_] = {0.0f, 0.0f, 0.0f, 0.0f};
    float wsum = 0.0f;
    #pragma unroll
    for (int s = 0; s < 4; s++) {
        const float vw = svw[s * 32 + pixL];
        wsum += vw;
        #pragma unroll
        for (int d = 0; d < D_; d++)
            simsum[d] = fmaf(ssim[((s * 4 + d) * 32 + pixL) * 9 + g], vw, simsum[d]);
    }
    const float invw = 1.0f / wsum;
    #pragma unroll
    for (int d = 0; d < D_; d++)
        out[(size_t)(g * D_ + d) * HW_ + pix] = simsum[d] * invw;
}

extern "C" void kernel_launch(void* const* d_in, const int* in_sizes, int n_in,
                              void* d_out, int out_size) {
    const float* features = (const float*)d_in[0];  // (5,1,32,384,384)
    const float* depths   = (const float*)d_in[1];  // (1,4,384,384)
    const float* Kall     = (const float*)d_in[2];  // (1,5,3,3)
    const float* Eall     = (const float*)d_in[3];  // (1,5,3,4)
    const float* w0 = (const float*)d_in[4];
    const float* b0 = (const float*)d_in[5];
    const float* w1 = (const float*)d_in[6];
    const float* b1 = (const float*)d_in[7];
    const float* w2 = (const float*)d_in[8];
    const float* b2 = (const float*)d_in[9];
    float* out = (float*)d_out;
    (void)in_sizes; (void)n_in; (void)out_size;

    dim3 tb(32, 32);
    transpose_setup_kernel<<<NTB * V_ + 1, tb>>>(features, Kall, Eall);

    gbinet_main_kernel<<<HW_ / 32, 256>>>(depths, w0, b0, w1, b1, w2, b2, out);
}

// round 6
// speedup vs baseline: 1.0135x; 1.0135x over previous
#include <cuda_runtime.h>
#include <cuda_fp16.h>
#include <cuda_bf16.h>
#include <math.h>

#define V_  5
#define C_  32
#define H_  384
#define W_  384
#define D_  4
#define G_  8
#define HW_ (H_ * W_)          // 147456
#define NTB (HW_ / 32)         // transpose blocks per view: 4608

// Reference view (view 0) transposed, fp32: (H*W, C)
__device__ float  g_refT[(size_t)HW_ * C_];            // 18.9 MB
// Source views (1..4) transposed, fp16: (4, H*W, C)  -- L2-resident (37.7 MB)
__device__ __half g_srcT[(size_t)4 * HW_ * C_];
// Folded projection per source view: uvd = M_s * (gx,gy,1) * dep + c_s
__device__ float g_M[4][9];
__device__ float g_c[4][3];

__device__ __forceinline__ void invert3f(const float* m, float* inv) {
    float a = m[0], b = m[1], c = m[2];
    float d = m[3], e = m[4], f = m[5];
    float g = m[6], h = m[7], i = m[8];
    float A  =  (e*i - f*h);
    float Bc = -(d*i - f*g);
    float Cc =  (d*h - e*g);
    float det = a*A + b*Bc + c*Cc;
    float id = 1.0f / det;
    inv[0] = A * id;
    inv[1] = -(b*i - c*h) * id;
    inv[2] =  (b*f - c*e) * id;
    inv[3] = Bc * id;
    inv[4] =  (a*i - c*g) * id;
    inv[5] = -(a*f - c*d) * id;
    inv[6] = Cc * id;
    inv[7] = -(a*h - b*g) * id;
    inv[8] =  (a*e - b*d) * id;
}

__device__ __forceinline__ void mat3mulf(const float* A, const float* B, float* Cm) {
    #pragma unroll
    for (int i = 0; i < 3; i++)
        #pragma unroll
        for (int j = 0; j < 3; j++)
            Cm[i*3+j] = A[i*3+0]*B[0*3+j] + A[i*3+1]*B[1*3+j] + A[i*3+2]*B[2*3+j];
}

// Fused: blocks [0, NTB*V) transpose CHW->HWC (view0 fp32, views1..4 fp16);
// block NTB*V folds cameras in fp32 on 4 threads.
__global__ void transpose_setup_kernel(const float* __restrict__ f,
                                       const float* __restrict__ K,
                                       const float* __restrict__ E) {
    if (blockIdx.x == NTB * V_) {
        const int s = threadIdx.x + threadIdx.y * 32;
        if (s < 4) {
            float K0[9], Kinv[9], R0[9], Rinv[9], t0[3];
            #pragma unroll
            for (int i = 0; i < 9; i++) K0[i] = K[i];
            invert3f(K0, Kinv);
            #pragma unroll
            for (int i = 0; i < 3; i++) {
                #pragma unroll
                for (int j = 0; j < 3; j++) R0[i*3+j] = E[i*4+j];
                t0[i] = E[i*4+3];
            }
            invert3f(R0, Rinv);

            float Ks[9], Rs[9], ts[3];
            #pragma unroll
            for (int i = 0; i < 9; i++) Ks[i] = K[(s+1)*9 + i];
            #pragma unroll
            for (int i = 0; i < 3; i++) {
                #pragma unroll
                for (int j = 0; j < 3; j++) Rs[i*3+j] = E[(s+1)*12 + i*4 + j];
                ts[i] = E[(s+1)*12 + i*4 + 3];
            }
            float A[9], Bm[9], M[9];
            mat3mulf(Rs, Rinv, A);
            mat3mulf(Ks, A, Bm);
            mat3mulf(Bm, Kinv, M);
            #pragma unroll
            for (int i = 0; i < 3; i++) {
                float kt = Ks[i*3+0]*ts[0] + Ks[i*3+1]*ts[1] + Ks[i*3+2]*ts[2];
                float bt = Bm[i*3+0]*t0[0] + Bm[i*3+1]*t0[1] + Bm[i*3+2]*t0[2];
                g_c[s][i] = kt - bt;
            }
            #pragma unroll
            for (int i = 0; i < 9; i++) g_M[s][i] = M[i];
        }
        return;
    }
    __shared__ float sbuf[32][33];
    const int v  = blockIdx.x / NTB;
    const int p0 = (blockIdx.x - v * NTB) * 32;
    const int tx = threadIdx.x, ty = threadIdx.y;
    sbuf[ty][tx] = f[((size_t)v * C_ + ty) * HW_ + p0 + tx];
    __syncthreads();
    if (v == 0) {
        g_refT[(size_t)(p0 + ty) * C_ + tx] = sbuf[tx][ty];
    } else {
        g_srcT[((size_t)(v - 1) * HW_ + (p0 + ty)) * C_ + tx] = __float2half(sbuf[tx][ty]);
    }
}

// Main kernel: 256 threads = 32 pixels x 8 group-lanes.
__global__ void __launch_bounds__(256, 5)
gbinet_main_kernel(const float* __restrict__ depths,
                   const float* __restrict__ w0, const float* __restrict__ b0,
                   const float* __restrict__ w1, const float* __restrict__ b1,
                   const float* __restrict__ w2, const float* __restrict__ b2,
                   float* __restrict__ out) {
    __shared__ float sw0[16*8], sb0[16], sw1[8*16], sb1[8], sw2[8], sb2v[1];
    __shared__ float sM[4][9], sc[4][3];
    __shared__ float ssim[4 * 4 * 32 * 9];   // [s][d][pixL][g(pad 9)] = 18 KB
    __shared__ float ssig[4 * 4 * 32];       // [s][d][pixL]
    __shared__ float svw[4 * 32];            // [s][pixL]

    const int tid  = threadIdx.x;
    const int pixL = tid >> 3;
    const int g    = tid & 7;

    if (tid < 128) sw0[tid] = w0[tid];
    else           sw1[tid - 128] = w1[tid - 128];
    if (tid < 16) sb0[tid] = b0[tid];
    if (tid >= 16 && tid < 24) sb1[tid - 16] = b1[tid - 16];
    if (tid >= 24 && tid < 32) sw2[tid - 24] = w2[tid - 24];
    if (tid == 32) sb2v[0] = b2[0];
    if (tid >= 64 && tid < 64 + 36) {
        int i = tid - 64; sM[i / 9][i % 9] = g_M[i / 9][i % 9];
    }
    if (tid >= 100 && tid < 112) {
        int i = tid - 100; sc[i / 3][i % 3] = g_c[i / 3][i % 3];
    }

    const int pix = blockIdx.x * 32 + pixL;
    const int y = pix / W_;
    const int x = pix - y * W_;
    const float gx = (float)x + 0.5f;
    const float gy = (float)y + 0.5f;

    float dep[D_];
    #pragma unroll
    for (int d = 0; d < D_; d++) dep[d] = depths[d * HW_ + pix];

    const float4 ref = ((const float4*)g_refT)[(size_t)pix * 8 + g];
    const uint2* __restrict__ src2 = (const uint2*)g_srcT;

    __syncthreads();   // weights + M/c visible

    // ---- gather phase: branchless bilinear over fp16 src (L2-resident) ----
    for (int s = 0; s < 4; s++) {
        const float mx = sM[s][0]*gx + sM[s][1]*gy + sM[s][2];
        const float my = sM[s][3]*gx + sM[s][4]*gy + sM[s][5];
        const float mz = sM[s][6]*gx + sM[s][7]*gy + sM[s][8];
        const size_t vbase = (size_t)s * HW_;
        #pragma unroll
        for (int d = 0; d < D_; d++) {
            const float uh = fmaf(mx, dep[d], sc[s][0]);
            const float vh = fmaf(my, dep[d], sc[s][1]);
            const float zh = fmaf(mz, dep[d], sc[s][2]);
            const float rz = 1.0f / (zh + 1e-9f);
            const float px = uh * rz;
            const float py = vh * rz;

            const float x0f = floorf(px);
            const float y0f = floorf(py);
            const float wx1 = px - x0f, wx0v = 1.0f - wx1;
            const float wy1 = py - y0f, wy0v = 1.0f - wy1;

            float acc = 0.0f;
            #pragma unroll
            for (int corner = 0; corner < 4; corner++) {
                const float xf = x0f + (float)(corner & 1);
                const float yf = y0f + (float)(corner >> 1);
                float w = ((corner & 1) ? wx1 : wx0v) *
                          ((corner >> 1) ? wy1 : wy0v);
                const bool valid = (xf >= 0.0f) & (xf <= (float)(W_ - 1)) &
                                   (yf >= 0.0f) & (yf <= (float)(H_ - 1));
                w = valid ? w : 0.0f;
                const int xi = min(max((int)xf, 0), W_ - 1);
                const int yi = min(max((int)yf, 0), H_ - 1);
                uint2 q = __ldg(src2 + (vbase + (size_t)yi * W_ + xi) * 8 + g);
                const __half2 h01 = *reinterpret_cast<__half2*>(&q.x);
                const __half2 h23 = *reinterpret_cast<__half2*>(&q.y);
                const float2 f01 = __half22float2(h01);
                const float2 f23 = __half22float2(h23);
                const float dot = f01.x*ref.x + f01.y*ref.y +
                                  f23.x*ref.z + f23.y*ref.w;
                acc = fmaf(w, dot, acc);
            }
            ssim[((s * 4 + d) * 32 + pixL) * 9 + g] = 0.25f * acc;
        }
    }
    __syncthreads();

    // ---- MLP phase: 512 (s,d,pix) items over 256 threads, 2 each ----
    #pragma unroll
    for (int it = 0; it < 2; it++) {
        const int i  = tid + it * 256;
        const int pp = i & 31;
        const int d  = (i >> 5) & 3;
        const int s  = i >> 7;
        const int base = ((s * 4 + d) * 32 + pp) * 9;
        float sv[8];
        #pragma unroll
        for (int k = 0; k < 8; k++) sv[k] = ssim[base + k];

        float x0v[16];
        #pragma unroll
        for (int o = 0; o < 16; o++) {
            float t = sb0[o];
            #pragma unroll
            for (int k = 0; k < 8; k++) t = fmaf(sw0[o*8 + k], sv[k], t);
            x0v[o] = fmaxf(t, 0.0f);
        }
        float x1v[8];
        #pragma unroll
        for (int j = 0; j < 8; j++) {
            float t = sb1[j];
            #pragma unroll
            for (int o = 0; o < 16; o++) t = fmaf(sw1[j*16 + o], x0v[o], t);
            x1v[j] = fmaxf(t, 0.0f);
        }
        float yv = sb2v[0];
        #pragma unroll
        for (int j = 0; j < 8; j++) yv = fmaf(sw2[j], x1v[j], yv);
        ssig[(s * 4 + d) * 32 + pp] = 1.0f / (1.0f + expf(-yv));
    }
    __syncthreads();

    // ---- depth max: vw[s][pix] = max_d sigmoid ----
    if (tid < 128) {
        const int s  = tid >> 5;
        const int pp = tid & 31;
        float m = ssig[(s * 4 + 0) * 32 + pp];
        #pragma unroll
        for (int d = 1; d < 4; d++) m = fmaxf(m, ssig[(s * 4 + d) * 32 + pp]);
        svw[s * 32 + pp] = m;
    }
    __syncthreads();

    // ---- accumulate + output ----
    float simsum[D_] = {0.0f, 0.0f, 0.0f, 0.0f};
    float wsum = 0.0f;
    #pragma unroll
    for (int s = 0; s < 4; s++) {
        const float vw = svw[s * 32 + pixL];
        wsum += vw;
        #pragma unroll
        for (int d = 0; d < D_; d++)
            simsum[d] = fmaf(ssim[((s * 4 + d) * 32 + pixL) * 9 + g], vw, simsum[d]);
    }
    const float invw = 1.0f / wsum;
    #pragma unroll
    for (int d = 0; d < D_; d++)
        out[(size_t)(g * D_ + d) * HW_ + pix] = simsum[d] * invw;
}

extern "C" void kernel_launch(void* const* d_in, const int* in_sizes, int n_in,
                              void* d_out, int out_size) {
    const float* features = (const float*)d_in[0];  // (5,1,32,384,384)
    const float* depths   = (const float*)d_in[1];  // (1,4,384,384)
    const float* Kall     = (const float*)d_in[2];  // (1,5,3,3)
    const float* Eall     = (const float*)d_in[3];  // (1,5,3,4)
    const float* w0 = (const float*)d_in[4];
    const float* b0 = (const float*)d_in[5];
    const float* w1 = (const float*)d_in[6];
    const float* b1 = (const float*)d_in[7];
    const float* w2 = (const float*)d_in[8];
    const float* b2 = (const float*)d_in[9];
    float* out = (float*)d_out;
    (void)in_sizes; (void)n_in; (void)out_size;

    dim3 tb(32, 32);
    transpose_setup_kernel<<<NTB * V_ + 1, tb>>>(features, Kall, Eall);

    gbinet_main_kernel<<<HW_ / 32, 256>>>(depths, w0, b0, w1, b1, w2, b2, out);
}

// round 8
// speedup vs baseline: 1.4163x; 1.3974x over previous
#include <cuda_runtime.h>
#include <cuda_bf16.h>
#include <math.h>

#define V_  5
#define C_  32
#define H_  384
#define W_  384
#define D_  4
#define G_  8
#define HW_ (H_ * W_)          // 147456
#define NTB (HW_ / 32)         // transpose blocks per view: 4608

// Transposed features (V, H*W, C): per-pixel channels contiguous, fp32.
__device__ float g_featT[(size_t)V_ * HW_ * C_];   // ~94.4 MB
// Folded projection per source view: uvd = M_s * (gx,gy,1) * dep + c_s
__device__ float g_M[4][9];
__device__ float g_c[4][3];

__device__ __forceinline__ void invert3f(const float* m, float* inv) {
    float a = m[0], b = m[1], c = m[2];
    float d = m[3], e = m[4], f = m[5];
    float g = m[6], h = m[7], i = m[8];
    float A  =  (e*i - f*h);
    float Bc = -(d*i - f*g);
    float Cc =  (d*h - e*g);
    float det = a*A + b*Bc + c*Cc;
    float id = 1.0f / det;
    inv[0] = A * id;
    inv[1] = -(b*i - c*h) * id;
    inv[2] =  (b*f - c*e) * id;
    inv[3] = Bc * id;
    inv[4] =  (a*i - c*g) * id;
    inv[5] = -(a*f - c*d) * id;
    inv[6] = Cc * id;
    inv[7] = -(a*h - b*g) * id;
    inv[8] =  (a*e - b*d) * id;
}

__device__ __forceinline__ void mat3mulf(const float* A, const float* B, float* Cm) {
    #pragma unroll
    for (int i = 0; i < 3; i++)
        #pragma unroll
        for (int j = 0; j < 3; j++)
            Cm[i*3+j] = A[i*3+0]*B[0*3+j] + A[i*3+1]*B[1*3+j] + A[i*3+2]*B[2*3+j];
}

// Fused: blocks [0, NTB*V) transpose CHW->HWC; block NTB*V folds cameras (fp32).
__global__ void transpose_setup_kernel(const float* __restrict__ f,
                                       const float* __restrict__ K,
                                       const float* __restrict__ E) {
    if (blockIdx.x == NTB * V_) {
        const int s = threadIdx.x + threadIdx.y * 32;
        if (s < 4) {
            float K0[9], Kinv[9], R0[9], Rinv[9], t0[3];
            #pragma unroll
            for (int i = 0; i < 9; i++) K0[i] = K[i];
            invert3f(K0, Kinv);
            #pragma unroll
            for (int i = 0; i < 3; i++) {
                #pragma unroll
                for (int j = 0; j < 3; j++) R0[i*3+j] = E[i*4+j];
                t0[i] = E[i*4+3];
            }
            invert3f(R0, Rinv);

            float Ks[9], Rs[9], ts[3];
            #pragma unroll
            for (int i = 0; i < 9; i++) Ks[i] = K[(s+1)*9 + i];
            #pragma unroll
            for (int i = 0; i < 3; i++) {
                #pragma unroll
                for (int j = 0; j < 3; j++) Rs[i*3+j] = E[(s+1)*12 + i*4 + j];
                ts[i] = E[(s+1)*12 + i*4 + 3];
            }
            float A[9], Bm[9], M[9];
            mat3mulf(Rs, Rinv, A);
            mat3mulf(Ks, A, Bm);
            mat3mulf(Bm, Kinv, M);
            #pragma unroll
            for (int i = 0; i < 3; i++) {
                float kt = Ks[i*3+0]*ts[0] + Ks[i*3+1]*ts[1] + Ks[i*3+2]*ts[2];
                float bt = Bm[i*3+0]*t0[0] + Bm[i*3+1]*t0[1] + Bm[i*3+2]*t0[2];
                g_c[s][i] = kt - bt;
            }
            #pragma unroll
            for (int i = 0; i < 9; i++) g_M[s][i] = M[i];
        }
        return;
    }
    __shared__ float sbuf[32][33];
    const int v  = blockIdx.x / NTB;
    const int p0 = (blockIdx.x - v * NTB) * 32;
    const int tx = threadIdx.x, ty = threadIdx.y;
    sbuf[ty][tx] = f[((size_t)v * C_ + ty) * HW_ + p0 + tx];
    __syncthreads();
    g_featT[(size_t)v * HW_ * C_ + (size_t)(p0 + ty) * C_ + tx] = sbuf[tx][ty];
}

// Streaming store for output.
__device__ __forceinline__ void stg_cs(float* p, float v) {
    asm volatile("st.global.cs.f32 [%0], %1;" :: "l"(p), "f"(v) : "memory");
}

// Main kernel: 256 threads = 32 pixels x 8 group-lanes.
__global__ void __launch_bounds__(256)
gbinet_main_kernel(const float* __restrict__ depths,
                   const float* __restrict__ w0, const float* __restrict__ b0,
                   const float* __restrict__ w1, const float* __restrict__ b1,
                   const float* __restrict__ w2, const float* __restrict__ b2,
                   float* __restrict__ out) {
    __shared__ float sw0[16*8], sb0[16], sw1[8*16], sb1[8], sw2[8], sb2v[1];
    __shared__ float sM[4][9], sc[4][3];
    __shared__ float ssim[4 * 4 * 32 * 9];   // [s][d][pixL][g(pad 9)] = 18 KB
    __shared__ float ssig[4 * 4 * 32];       // [s][d][pixL]
    __shared__ float svw[4 * 32];            // [s][pixL]

    const int tid  = threadIdx.x;
    const int pixL = tid >> 3;
    const int g    = tid & 7;

    if (tid < 128) sw0[tid] = w0[tid];
    else           sw1[tid - 128] = w1[tid - 128];
    if (tid < 16) sb0[tid] = b0[tid];
    if (tid >= 16 && tid < 24) sb1[tid - 16] = b1[tid - 16];
    if (tid >= 24 && tid < 32) sw2[tid - 24] = w2[tid - 24];
    if (tid == 32) sb2v[0] = b2[0];
    if (tid >= 64 && tid < 64 + 36) {
        int i = tid - 64; sM[i / 9][i % 9] = g_M[i / 9][i % 9];
    }
    if (tid >= 100 && tid < 112) {
        int i = tid - 100; sc[i / 3][i % 3] = g_c[i / 3][i % 3];
    }

    const int pix = blockIdx.x * 32 + pixL;
    const int y = pix / W_;
    const int x = pix - y * W_;
    const float gx = (float)x + 0.5f;
    const float gy = (float)y + 0.5f;

    float dep[D_];
    #pragma unroll
    for (int d = 0; d < D_; d++) dep[d] = depths[d * HW_ + pix];

    const float4* __restrict__ fT4 = (const float4*)g_featT;
    const float4 ref = fT4[(size_t)pix * 8 + g];

    __syncthreads();   // weights + M/c visible

    // ---- gather phase: branchy bilinear (skip OOB loads) ----
    for (int s = 0; s < 4; s++) {
        const float mx = sM[s][0]*gx + sM[s][1]*gy + sM[s][2];
        const float my = sM[s][3]*gx + sM[s][4]*gy + sM[s][5];
        const float mz = sM[s][6]*gx + sM[s][7]*gy + sM[s][8];
        const size_t vbase = (size_t)(s + 1) * HW_;
        #pragma unroll
        for (int d = 0; d < D_; d++) {
            const float uh = fmaf(mx, dep[d], sc[s][0]);
            const float vh = fmaf(my, dep[d], sc[s][1]);
            const float zh = fmaf(mz, dep[d], sc[s][2]);
            const float rz = 1.0f / (zh + 1e-9f);
            const float px = uh * rz;
            const float py = vh * rz;

            const float x0f = floorf(px);
            const float y0f = floorf(py);
            const float wx1 = px - x0f, wx0v = 1.0f - wx1;
            const float wy1 = py - y0f, wy0v = 1.0f - wy1;

            float acc = 0.0f;
            #pragma unroll
            for (int corner = 0; corner < 4; corner++) {
                const float xf = x0f + (float)(corner & 1);
                const float yf = y0f + (float)(corner >> 1);
                const float w = ((corner & 1) ? wx1 : wx0v) *
                                ((corner >> 1) ? wy1 : wy0v);
                if (xf >= 0.0f && xf <= (float)(W_ - 1) &&
                    yf >= 0.0f && yf <= (float)(H_ - 1)) {
                    const int xi = (int)xf;
                    const int yi = (int)yf;
                    const float4 f = __ldg(fT4 + (vbase + (size_t)yi * W_ + xi) * 8 + g);
                    const float dot = f.x*ref.x + f.y*ref.y + f.z*ref.z + f.w*ref.w;
                    acc = fmaf(w, dot, acc);
                }
            }
            ssim[((s * 4 + d) * 32 + pixL) * 9 + g] = 0.25f * acc;
        }
    }
    __syncthreads();

    // ---- MLP phase: 512 (s,d,pix) items over 256 threads, 2 each ----
    #pragma unroll
    for (int it = 0; it < 2; it++) {
        const int i  = tid + it * 256;
        const int pp = i & 31;
        const int d  = (i >> 5) & 3;
        const int s  = i >> 7;
        const int base = ((s * 4 + d) * 32 + pp) * 9;
        float sv[8];
        #pragma unroll
        for (int k = 0; k < 8; k++) sv[k] = ssim[base + k];

        float x0v[16];
        #pragma unroll
        for (int o = 0; o < 16; o++) {
            float t = sb0[o];
            #pragma unroll
            for (int k = 0; k < 8; k++) t = fmaf(sw0[o*8 + k], sv[k], t);
            x0v[o] = fmaxf(t, 0.0f);
        }
        float x1v[8];
        #pragma unroll
        for (int j = 0; j < 8; j++) {
            float t = sb1[j];
            #pragma unroll
            for (int o = 0; o < 16; o++) t = fmaf(sw1[j*16 + o], x0v[o], t);
            x1v[j] = fmaxf(t, 0.0f);
        }
        float yv = sb2v[0];
        #pragma unroll
        for (int j = 0; j < 8; j++) yv = fmaf(sw2[j], x1v[j], yv);
        ssig[(s * 4 + d) * 32 + pp] = 1.0f / (1.0f + expf(-yv));
    }
    __syncthreads();

    // ---- depth max: vw[s][pix] = max_d sigmoid ----
    if (tid < 128) {
        const int s  = tid >> 5;
        const int pp = tid & 31;
        float m = ssig[(s * 4 + 0) * 32 + pp];
        #pragma unroll
        for (int d = 1; d < 4; d++) m = fmaxf(m, ssig[(s * 4 + d) * 32 + pp]);
        svw[s * 32 + pp] = m;
    }
    __syncthreads();

    // ---- accumulate + output (streaming stores) ----
    float simsum[D_] = {0.0f, 0.0f, 0.0f, 0.0f};
    float wsum = 0.0f;
    #pragma unroll
    for (int s = 0; s < 4; s++) {
        const float vw = svw[s * 32 + pixL];
        wsum += vw;
        #pragma unroll
        for (int d = 0; d < D_; d++)
            simsum[d] = fmaf(ssim[((s * 4 + d) * 32 + pixL) * 9 + g], vw, simsum[d]);
    }
    const float invw = 1.0f / wsum;
    #pragma unroll
    for (int d = 0; d < D_; d++)
        stg_cs(out + (size_t)(g * D_ + d) * HW_ + pix, simsum[d] * invw);
}

extern "C" void kernel_launch(void* const* d_in, const int* in_sizes, int n_in,
                              void* d_out, int out_size) {
    const float* features = (const float*)d_in[0];  // (5,1,32,384,384)
    const float* depths   = (const float*)d_in[1];  // (1,4,384,384)
    const float* Kall     = (const float*)d_in[2];  // (1,5,3,3)
    const float* Eall     = (const float*)d_in[3];  // (1,5,3,4)
    const float* w0 = (const float*)d_in[4];
    const float* b0 = (const float*)d_in[5];
    const float* w1 = (const float*)d_in[6];
    const float* b1 = (const float*)d_in[7];
    const float* w2 = (const float*)d_in[8];
    const float* b2 = (const float*)d_in[9];
    float* out = (float*)d_out;
    (void)in_sizes; (void)n_in; (void)out_size;

    dim3 tb(32, 32);
    transpose_setup_kernel<<<NTB * V_ + 1, tb>>>(features, Kall, Eall);

    gbinet_main_kernel<<<HW_ / 32, 256>>>(depths, w0, b0, w1, b1, w2, b2, out);
}

// round 9
// speedup vs baseline: 1.4887x; 1.0511x over previous
#include <cuda_runtime.h>
#include <cuda_bf16.h>
#include <math.h>

#define V_  5
#define C_  32
#define H_  384
#define W_  384
#define D_  4
#define G_  8
#define HW_ (H_ * W_)          // 147456
#define NPT (HW_ / 128)        // transpose blocks per view: 1152

// Transposed features (V, H*W, C): per-pixel channels contiguous, fp32.
__device__ float g_featT[(size_t)V_ * HW_ * C_];   // ~94.4 MB
// Folded projection per source view: uvd = M_s * (gx,gy,1) * dep + c_s
__device__ float g_M[4][9];
__device__ float g_c[4][3];

__device__ __forceinline__ void invert3f(const float* m, float* inv) {
    float a = m[0], b = m[1], c = m[2];
    float d = m[3], e = m[4], f = m[5];
    float g = m[6], h = m[7], i = m[8];
    float A  =  (e*i - f*h);
    float Bc = -(d*i - f*g);
    float Cc =  (d*h - e*g);
    float det = a*A + b*Bc + c*Cc;
    float id = 1.0f / det;
    inv[0] = A * id;
    inv[1] = -(b*i - c*h) * id;
    inv[2] =  (b*f - c*e) * id;
    inv[3] = Bc * id;
    inv[4] =  (a*i - c*g) * id;
    inv[5] = -(a*f - c*d) * id;
    inv[6] = Cc * id;
    inv[7] = -(a*h - b*g) * id;
    inv[8] =  (a*e - b*d) * id;
}

__device__ __forceinline__ void mat3mulf(const float* A, const float* B, float* Cm) {
    #pragma unroll
    for (int i = 0; i < 3; i++)
        #pragma unroll
        for (int j = 0; j < 3; j++)
            Cm[i*3+j] = A[i*3+0]*B[0*3+j] + A[i*3+1]*B[1*3+j] + A[i*3+2]*B[2*3+j];
}

// Fused: blocks [0, NPT*V) transpose CHW->HWC (128 pixels per block, 4 tiles);
// block NPT*V folds cameras (fp32, 4 threads).
__global__ void __launch_bounds__(1024)
transpose_setup_kernel(const float* __restrict__ f,
                       const float* __restrict__ K,
                       const float* __restrict__ E) {
    if (blockIdx.x == NPT * V_) {
        const int s = threadIdx.x + threadIdx.y * 32;
        if (s < 4) {
            float K0[9], Kinv[9], R0[9], Rinv[9], t0[3];
            #pragma unroll
            for (int i = 0; i < 9; i++) K0[i] = K[i];
            invert3f(K0, Kinv);
            #pragma unroll
            for (int i = 0; i < 3; i++) {
                #pragma unroll
                for (int j = 0; j < 3; j++) R0[i*3+j] = E[i*4+j];
                t0[i] = E[i*4+3];
            }
            invert3f(R0, Rinv);

            float Ks[9], Rs[9], ts[3];
            #pragma unroll
            for (int i = 0; i < 9; i++) Ks[i] = K[(s+1)*9 + i];
            #pragma unroll
            for (int i = 0; i < 3; i++) {
                #pragma unroll
                for (int j = 0; j < 3; j++) Rs[i*3+j] = E[(s+1)*12 + i*4 + j];
                ts[i] = E[(s+1)*12 + i*4 + 3];
            }
            float A[9], Bm[9], M[9];
            mat3mulf(Rs, Rinv, A);
            mat3mulf(Ks, A, Bm);
            mat3mulf(Bm, Kinv, M);
            #pragma unroll
            for (int i = 0; i < 3; i++) {
                float kt = Ks[i*3+0]*ts[0] + Ks[i*3+1]*ts[1] + Ks[i*3+2]*ts[2];
                float bt = Bm[i*3+0]*t0[0] + Bm[i*3+1]*t0[1] + Bm[i*3+2]*t0[2];
                g_c[s][i] = kt - bt;
            }
            #pragma unroll
            for (int i = 0; i < 9; i++) g_M[s][i] = M[i];
        }
        return;
    }
    __shared__ float sbuf[4][32][33];
    const int v  = blockIdx.x / NPT;
    const int p0 = (blockIdx.x - v * NPT) * 128;
    const int tx = threadIdx.x, ty = threadIdx.y;
    // 4 independent loads per thread (MLP=4), coalesced in pixels
    #pragma unroll
    for (int t = 0; t < 4; t++)
        sbuf[t][ty][tx] = f[((size_t)v * C_ + ty) * HW_ + p0 + t * 32 + tx];
    __syncthreads();
    // 4 independent stores, coalesced in channels
    #pragma unroll
    for (int t = 0; t < 4; t++)
        g_featT[(size_t)v * HW_ * C_ + (size_t)(p0 + t * 32 + ty) * C_ + tx] =
            sbuf[t][tx][ty];
}

// Streaming store for output.
__device__ __forceinline__ void stg_cs(float* p, float v) {
    asm volatile("st.global.cs.f32 [%0], %1;" :: "l"(p), "f"(v) : "memory");
}

// Main kernel: 256 threads = 32 pixels x 8 group-lanes. 3 blocks/SM (85 regs).
__global__ void __launch_bounds__(256, 3)
gbinet_main_kernel(const float* __restrict__ depths,
                   const float* __restrict__ w0, const float* __restrict__ b0,
                   const float* __restrict__ w1, const float* __restrict__ b1,
                   const float* __restrict__ w2, const float* __restrict__ b2,
                   float* __restrict__ out) {
    __shared__ float sw0[16*8], sb0[16], sw1[8*16], sb1[8], sw2[8], sb2v[1];
    __shared__ float sM[4][9], sc[4][3];
    __shared__ float ssim[4 * 4 * 32 * 9];   // [s][d][pixL][g(pad 9)] = 18 KB
    __shared__ float ssig[4 * 4 * 32];       // [s][d][pixL]
    __shared__ float svw[4 * 32];            // [s][pixL]

    const int tid  = threadIdx.x;
    const int pixL = tid >> 3;
    const int g    = tid & 7;

    if (tid < 128) sw0[tid] = w0[tid];
    else           sw1[tid - 128] = w1[tid - 128];
    if (tid < 16) sb0[tid] = b0[tid];
    if (tid >= 16 && tid < 24) sb1[tid - 16] = b1[tid - 16];
    if (tid >= 24 && tid < 32) sw2[tid - 24] = w2[tid - 24];
    if (tid == 32) sb2v[0] = b2[0];
    if (tid >= 64 && tid < 64 + 36) {
        int i = tid - 64; sM[i / 9][i % 9] = g_M[i / 9][i % 9];
    }
    if (tid >= 100 && tid < 112) {
        int i = tid - 100; sc[i / 3][i % 3] = g_c[i / 3][i % 3];
    }

    const int pix = blockIdx.x * 32 + pixL;
    const int y = pix / W_;
    const int x = pix - y * W_;
    const float gx = (float)x + 0.5f;
    const float gy = (float)y + 0.5f;

    float dep[D_];
    #pragma unroll
    for (int d = 0; d < D_; d++) dep[d] = depths[d * HW_ + pix];

    const float4* __restrict__ fT4 = (const float4*)g_featT;
    const float4 ref = fT4[(size_t)pix * 8 + g];

    __syncthreads();   // weights + M/c visible

    // ---- gather phase: one view's 16 gathers batched at a time ----
    #pragma unroll 1
    for (int s = 0; s < 4; s++) {
        const float mx = sM[s][0]*gx + sM[s][1]*gy + sM[s][2];
        const float my = sM[s][3]*gx + sM[s][4]*gy + sM[s][5];
        const float mz = sM[s][6]*gx + sM[s][7]*gy + sM[s][8];
        const size_t vbase = (size_t)(s + 1) * HW_;
        #pragma unroll
        for (int d = 0; d < D_; d++) {
            const float uh = fmaf(mx, dep[d], sc[s][0]);
            const float vh = fmaf(my, dep[d], sc[s][1]);
            const float zh = fmaf(mz, dep[d], sc[s][2]);
            const float rz = 1.0f / (zh + 1e-9f);
            const float px = uh * rz;
            const float py = vh * rz;

            const float x0f = floorf(px);
            const float y0f = floorf(py);
            const float wx1 = px - x0f, wx0v = 1.0f - wx1;
            const float wy1 = py - y0f, wy0v = 1.0f - wy1;

            float acc = 0.0f;
            #pragma unroll
            for (int corner = 0; corner < 4; corner++) {
                const float xf = x0f + (float)(corner & 1);
                const float yf = y0f + (float)(corner >> 1);
                const float w = ((corner & 1) ? wx1 : wx0v) *
                                ((corner >> 1) ? wy1 : wy0v);
                if (xf >= 0.0f && xf <= (float)(W_ - 1) &&
                    yf >= 0.0f && yf <= (float)(H_ - 1)) {
                    const int xi = (int)xf;
                    const int yi = (int)yf;
                    const float4 f = __ldg(fT4 + (vbase + (size_t)yi * W_ + xi) * 8 + g);
                    const float dot = f.x*ref.x + f.y*ref.y + f.z*ref.z + f.w*ref.w;
                    acc = fmaf(w, dot, acc);
                }
            }
            ssim[((s * 4 + d) * 32 + pixL) * 9 + g] = 0.25f * acc;
        }
    }
    __syncthreads();

    // ---- MLP phase: 512 (s,d,pix) items over 256 threads, 2 each ----
    #pragma unroll
    for (int it = 0; it < 2; it++) {
        const int i  = tid + it * 256;
        const int pp = i & 31;
        const int d  = (i >> 5) & 3;
        const int s  = i >> 7;
        const int base = ((s * 4 + d) * 32 + pp) * 9;
        float sv[8];
        #pragma unroll
        for (int k = 0; k < 8; k++) sv[k] = ssim[base + k];

        float x0v[16];
        #pragma unroll
        for (int o = 0; o < 16; o++) {
            float t = sb0[o];
            #pragma unroll
            for (int k = 0; k < 8; k++) t = fmaf(sw0[o*8 + k], sv[k], t);
            x0v[o] = fmaxf(t, 0.0f);
        }
        float x1v[8];
        #pragma unroll
        for (int j = 0; j < 8; j++) {
            float t = sb1[j];
            #pragma unroll
            for (int o = 0; o < 16; o++) t = fmaf(sw1[j*16 + o], x0v[o], t);
            x1v[j] = fmaxf(t, 0.0f);
        }
        float yv = sb2v[0];
        #pragma unroll
        for (int j = 0; j < 8; j++) yv = fmaf(sw2[j], x1v[j], yv);
        ssig[(s * 4 + d) * 32 + pp] = 1.0f / (1.0f + expf(-yv));
    }
    __syncthreads();

    // ---- depth max: vw[s][pix] = max_d sigmoid ----
    if (tid < 128) {
        const int s  = tid >> 5;
        const int pp = tid & 31;
        float m = ssig[(s * 4 + 0) * 32 + pp];
        #pragma unroll
        for (int d = 1; d < 4; d++) m = fmaxf(m, ssig[(s * 4 + d) * 32 + pp]);
        svw[s * 32 + pp] = m;
    }
    __syncthreads();

    // ---- accumulate + output (streaming stores) ----
    float simsum[D_] = {0.0f, 0.0f, 0.0f, 0.0f};
    float wsum = 0.0f;
    #pragma unroll
    for (int s = 0; s < 4; s++) {
        const float vw = svw[s * 32 + pixL];
        wsum += vw;
        #pragma unroll
        for (int d = 0; d < D_; d++)
            simsum[d] = fmaf(ssim[((s * 4 + d) * 32 + pixL) * 9 + g], vw, simsum[d]);
    }
    const float invw = 1.0f / wsum;
    #pragma unroll
    for (int d = 0; d < D_; d++)
        stg_cs(out + (size_t)(g * D_ + d) * HW_ + pix, simsum[d] * invw);
}

extern "C" void kernel_launch(void* const* d_in, const int* in_sizes, int n_in,
                              void* d_out, int out_size) {
    const float* features = (const float*)d_in[0];  // (5,1,32,384,384)
    const float* depths   = (const float*)d_in[1];  // (1,4,384,384)
    const float* Kall     = (const float*)d_in[2];  // (1,5,3,3)
    const float* Eall     = (const float*)d_in[3];  // (1,5,3,4)
    const float* w0 = (const float*)d_in[4];
    const float* b0 = (const float*)d_in[5];
    const float* w1 = (const float*)d_in[6];
    const float* b1 = (const float*)d_in[7];
    const float* w2 = (const float*)d_in[8];
    const float* b2 = (const float*)d_in[9];
    float* out = (float*)d_out;
    (void)in_sizes; (void)n_in; (void)out_size;

    dim3 tb(32, 32);
    transpose_setup_kernel<<<NPT * V_ + 1, tb>>>(features, Kall, Eall);

    gbinet_main_kernel<<<HW_ / 32, 256>>>(depths, w0, b0, w1, b1, w2, b2, out);
}

// round 10
// speedup vs baseline: 2.0429x; 1.3722x over previous
#include <cuda_runtime.h>
#include <cuda_bf16.h>
#include <math.h>

#define V_  5
#define C_  32
#define H_  384
#define W_  384
#define D_  4
#define G_  8
#define HW_ (H_ * W_)          // 147456
#define TPB_PIX 256            // pixels per transpose block
#define NPT (HW_ / TPB_PIX)    // transpose blocks per view: 576

// Transposed features (V, H*W, C): per-pixel channels contiguous, fp32.
__device__ float g_featT[(size_t)V_ * HW_ * C_];   // ~94.4 MB
// Folded projection per source view: uvd = M_s * (gx,gy,1) * dep + c_s
__device__ float g_M[4][9];
__device__ float g_c[4][3];

__device__ __forceinline__ void invert3f(const float* m, float* inv) {
    float a = m[0], b = m[1], c = m[2];
    float d = m[3], e = m[4], f = m[5];
    float g = m[6], h = m[7], i = m[8];
    float A  =  (e*i - f*h);
    float Bc = -(d*i - f*g);
    float Cc =  (d*h - e*g);
    float det = a*A + b*Bc + c*Cc;
    float id = 1.0f / det;
    inv[0] = A * id;
    inv[1] = -(b*i - c*h) * id;
    inv[2] =  (b*f - c*e) * id;
    inv[3] = Bc * id;
    inv[4] =  (a*i - c*g) * id;
    inv[5] = -(a*f - c*d) * id;
    inv[6] = Cc * id;
    inv[7] = -(a*h - b*g) * id;
    inv[8] =  (a*e - b*d) * id;
}

__device__ __forceinline__ void mat3mulf(const float* A, const float* B, float* Cm) {
    #pragma unroll
    for (int i = 0; i < 3; i++)
        #pragma unroll
        for (int j = 0; j < 3; j++)
            Cm[i*3+j] = A[i*3+0]*B[0*3+j] + A[i*3+1]*B[1*3+j] + A[i*3+2]*B[2*3+j];
}

// Fused: blocks [0, NPT*V) transpose CHW->HWC (256 pixels / 8 tiles per block);
// block NPT*V folds cameras (fp32, 4 threads).
__global__ void __launch_bounds__(1024)
transpose_setup_kernel(const float* __restrict__ f,
                       const float* __restrict__ K,
                       const float* __restrict__ E) {
    if (blockIdx.x == NPT * V_) {
        const int s = threadIdx.x + threadIdx.y * 32;
        if (s < 4) {
            float K0[9], Kinv[9], R0[9], Rinv[9], t0[3];
            #pragma unroll
            for (int i = 0; i < 9; i++) K0[i] = K[i];
            invert3f(K0, Kinv);
            #pragma unroll
            for (int i = 0; i < 3; i++) {
                #pragma unroll
                for (int j = 0; j < 3; j++) R0[i*3+j] = E[i*4+j];
                t0[i] = E[i*4+3];
            }
            invert3f(R0, Rinv);

            float Ks[9], Rs[9], ts[3];
            #pragma unroll
            for (int i = 0; i < 9; i++) Ks[i] = K[(s+1)*9 + i];
            #pragma unroll
            for (int i = 0; i < 3; i++) {
                #pragma unroll
                for (int j = 0; j < 3; j++) Rs[i*3+j] = E[(s+1)*12 + i*4 + j];
                ts[i] = E[(s+1)*12 + i*4 + 3];
            }
            float A[9], Bm[9], M[9];
            mat3mulf(Rs, Rinv, A);
            mat3mulf(Ks, A, Bm);
            mat3mulf(Bm, Kinv, M);
            #pragma unroll
            for (int i = 0; i < 3; i++) {
                float kt = Ks[i*3+0]*ts[0] + Ks[i*3+1]*ts[1] + Ks[i*3+2]*ts[2];
                float bt = Bm[i*3+0]*t0[0] + Bm[i*3+1]*t0[1] + Bm[i*3+2]*t0[2];
                g_c[s][i] = kt - bt;
            }
            #pragma unroll
            for (int i = 0; i < 9; i++) g_M[s][i] = M[i];
        }
        return;
    }
    __shared__ float sbuf[8][32][33];
    const int v  = blockIdx.x / NPT;
    const int p0 = (blockIdx.x - v * NPT) * TPB_PIX;
    const int tx = threadIdx.x, ty = threadIdx.y;
    // 8 independent loads per thread (MLP=8), coalesced in pixels
    #pragma unroll
    for (int t = 0; t < 8; t++)
        sbuf[t][ty][tx] = f[((size_t)v * C_ + ty) * HW_ + p0 + t * 32 + tx];
    __syncthreads();
    // 8 independent stores, coalesced in channels
    #pragma unroll
    for (int t = 0; t < 8; t++)
        g_featT[(size_t)v * HW_ * C_ + (size_t)(p0 + t * 32 + ty) * C_ + tx] =
            sbuf[t][tx][ty];
}

// Streaming store for output.
__device__ __forceinline__ void stg_cs(float* p, float v) {
    asm volatile("st.global.cs.f32 [%0], %1;" :: "l"(p), "f"(v) : "memory");
}

// Main kernel: 256 threads = 32 pixels x 8 group-lanes. 2 blocks/SM (128 regs),
// gathers batched 2 views (32 loads) at a time.
__global__ void __launch_bounds__(256, 2)
gbinet_main_kernel(const float* __restrict__ depths,
                   const float* __restrict__ w0, const float* __restrict__ b0,
                   const float* __restrict__ w1, const float* __restrict__ b1,
                   const float* __restrict__ w2, const float* __restrict__ b2,
                   float* __restrict__ out) {
    __shared__ float sw0[16*8], sb0[16], sw1[8*16], sb1[8], sw2[8], sb2v[1];
    __shared__ float sM[4][9], sc[4][3];
    __shared__ float ssim[4 * 4 * 32 * 9];   // [s][d][pixL][g(pad 9)] = 18 KB
    __shared__ float ssig[4 * 4 * 32];       // [s][d][pixL]
    __shared__ float svw[4 * 32];            // [s][pixL]

    const int tid  = threadIdx.x;
    const int pixL = tid >> 3;
    const int g    = tid & 7;

    if (tid < 128) sw0[tid] = w0[tid];
    else           sw1[tid - 128] = w1[tid - 128];
    if (tid < 16) sb0[tid] = b0[tid];
    if (tid >= 16 && tid < 24) sb1[tid - 16] = b1[tid - 16];
    if (tid >= 24 && tid < 32) sw2[tid - 24] = w2[tid - 24];
    if (tid == 32) sb2v[0] = b2[0];
    if (tid >= 64 && tid < 64 + 36) {
        int i = tid - 64; sM[i / 9][i % 9] = g_M[i / 9][i % 9];
    }
    if (tid >= 100 && tid < 112) {
        int i = tid - 100; sc[i / 3][i % 3] = g_c[i / 3][i % 3];
    }

    const int pix = blockIdx.x * 32 + pixL;
    const int y = pix / W_;
    const int x = pix - y * W_;
    const float gx = (float)x + 0.5f;
    const float gy = (float)y + 0.5f;

    float dep[D_];
    #pragma unroll
    for (int d = 0; d < D_; d++) dep[d] = depths[d * HW_ + pix];

    const float4* __restrict__ fT4 = (const float4*)g_featT;
    const float4 ref = fT4[(size_t)pix * 8 + g];

    __syncthreads();   // weights + M/c visible

    // ---- gather phase: 2 views (32 loads) batched per pass ----
    #pragma unroll 2
    for (int s = 0; s < 4; s++) {
        const float mx = sM[s][0]*gx + sM[s][1]*gy + sM[s][2];
        const float my = sM[s][3]*gx + sM[s][4]*gy + sM[s][5];
        const float mz = sM[s][6]*gx + sM[s][7]*gy + sM[s][8];
        const size_t vbase = (size_t)(s + 1) * HW_;
        #pragma unroll
        for (int d = 0; d < D_; d++) {
            const float uh = fmaf(mx, dep[d], sc[s][0]);
            const float vh = fmaf(my, dep[d], sc[s][1]);
            const float zh = fmaf(mz, dep[d], sc[s][2]);
            const float rz = 1.0f / (zh + 1e-9f);
            const float px = uh * rz;
            const float py = vh * rz;

            const float x0f = floorf(px);
            const float y0f = floorf(py);
            const float wx1 = px - x0f, wx0v = 1.0f - wx1;
            const float wy1 = py - y0f, wy0v = 1.0f - wy1;

            float acc = 0.0f;
            #pragma unroll
            for (int corner = 0; corner < 4; corner++) {
                const float xf = x0f + (float)(corner & 1);
                const float yf = y0f + (float)(corner >> 1);
                const float w = ((corner & 1) ? wx1 : wx0v) *
                                ((corner >> 1) ? wy1 : wy0v);
                if (xf >= 0.0f && xf <= (float)(W_ - 1) &&
                    yf >= 0.0f && yf <= (float)(H_ - 1)) {
                    const int xi = (int)xf;
                    const int yi = (int)yf;
                    const float4 f = __ldg(fT4 + (vbase + (size_t)yi * W_ + xi) * 8 + g);
                    const float dot = f.x*ref.x + f.y*ref.y + f.z*ref.z + f.w*ref.w;
                    acc = fmaf(w, dot, acc);
                }
            }
            ssim[((s * 4 + d) * 32 + pixL) * 9 + g] = 0.25f * acc;
        }
    }
    __syncthreads();

    // ---- MLP phase: 512 (s,d,pix) items over 256 threads, 2 each ----
    #pragma unroll
    for (int it = 0; it < 2; it++) {
        const int i  = tid + it * 256;
        const int pp = i & 31;
        const int d  = (i >> 5) & 3;
        const int s  = i >> 7;
        const int base = ((s * 4 + d) * 32 + pp) * 9;
        float sv[8];
        #pragma unroll
        for (int k = 0; k < 8; k++) sv[k] = ssim[base + k];

        float x0v[16];
        #pragma unroll
        for (int o = 0; o < 16; o++) {
            float t = sb0[o];
            #pragma unroll
            for (int k = 0; k < 8; k++) t = fmaf(sw0[o*8 + k], sv[k], t);
            x0v[o] = fmaxf(t, 0.0f);
        }
        float x1v[8];
        #pragma unroll
        for (int j = 0; j < 8; j++) {
            float t = sb1[j];
            #pragma unroll
            for (int o = 0; o < 16; o++) t = fmaf(sw1[j*16 + o], x0v[o], t);
            x1v[j] = fmaxf(t, 0.0f);
        }
        float yv = sb2v[0];
        #pragma unroll
        for (int j = 0; j < 8; j++) yv = fmaf(sw2[j], x1v[j], yv);
        ssig[(s * 4 + d) * 32 + pp] = 1.0f / (1.0f + expf(-yv));
    }
    __syncthreads();

    // ---- depth max: vw[s][pix] = max_d sigmoid ----
    if (tid < 128) {
        const int s  = tid >> 5;
        const int pp = tid & 31;
        float m = ssig[(s * 4 + 0) * 32 + pp];
        #pragma unroll
        for (int d = 1; d < 4; d++) m = fmaxf(m, ssig[(s * 4 + d) * 32 + pp]);
        svw[s * 32 + pp] = m;
    }
    __syncthreads();

    // ---- accumulate + output (streaming stores) ----
    float simsum[D_] = {0.0f, 0.0f, 0.0f, 0.0f};
    float wsum = 0.0f;
    #pragma unroll
    for (int s = 0; s < 4; s++) {
        const float vw = svw[s * 32 + pixL];
        wsum += vw;
        #pragma unroll
        for (int d = 0; d < D_; d++)
            simsum[d] = fmaf(ssim[((s * 4 + d) * 32 + pixL) * 9 + g], vw, simsum[d]);
    }
    const float invw = 1.0f / wsum;
    #pragma unroll
    for (int d = 0; d < D_; d++)
        stg_cs(out + (size_t)(g * D_ + d) * HW_ + pix, simsum[d] * invw);
}

extern "C" void kernel_launch(void* const* d_in, const int* in_sizes, int n_in,
                              void* d_out, int out_size) {
    const float* features = (const float*)d_in[0];  // (5,1,32,384,384)
    const float* depths   = (const float*)d_in[1];  // (1,4,384,384)
    const float* Kall     = (const float*)d_in[2];  // (1,5,3,3)
    const float* Eall     = (const float*)d_in[3];  // (1,5,3,4)
    const float* w0 = (const float*)d_in[4];
    const float* b0 = (const float*)d_in[5];
    const float* w1 = (const float*)d_in[6];
    const float* b1 = (const float*)d_in[7];
    const float* w2 = (const float*)d_in[8];
    const float* b2 = (const float*)d_in[9];
    float* out = (float*)d_out;
    (void)in_sizes; (void)n_in; (void)out_size;

    dim3 tb(32, 32);
    transpose_setup_kernel<<<NPT * V_ + 1, tb>>>(features, Kall, Eall);

    gbinet_main_kernel<<<HW_ / 32, 256>>>(depths, w0, b0, w1, b1, w2, b2, out);
}